// round 16
// baseline (speedup 1.0000x reference)
#include <cuda_runtime.h>
#include <cuda_fp16.h>
#include <math.h>
#include <stdint.h>

#define BATCH  256
#define PRIOR  60
#define FRAMES 240
#define POSE   768
#define CHUNK  10
#define PRED   180
#define EPS    1e-5f
#define MROWS  (BATCH * FRAMES)
#define CIN1P  64
#define CIN2P  192
#define KC1    (3 * CIN1P)
#define KC2    (3 * CIN2P)
#define XTR    770
#define KENC   (CHUNK * POSE)      // 7680

// ---------------- scratch (zero-initialized device globals; padding rows/channels are
// never written by any kernel, so they stay zero forever -> deterministic) -------------
__device__ unsigned short g_Ah[MROWS * POSE];                 // concat rows, fp16
__device__ unsigned short g_Hh[MROWS * POSE];                 // h1, fp16
__device__ unsigned short g_W1h[POSE * POSE];
__device__ unsigned short g_W2h[POSE * POSE];
__device__ unsigned short g_Xth[BATCH * XTR * CIN1P];         // xT padded, fp16
__device__ unsigned short g_P1h[BATCH * XTR * CIN2P];         // conv1 out (transposed), fp16
__device__ unsigned short g_Wc1h[256 * KC1];
__device__ unsigned short g_Wc2h[256 * KC2];
__device__ unsigned short g_Wm[2 * POSE * KENC];              // sp_w1 | tmc_w1 fp16
__device__ float          g_bm[2 * POSE];                     // sp_b1 | tmc_b1
__device__ unsigned short g_W2sh[POSE * POSE];                // sp_w2 fp16
__device__ unsigned short g_W2th[POSE * POSE];                // tmc_w2 fp16
__device__ unsigned short g_tmph[BATCH * 2 * POSE];           // enc layer-1 out fp16, ld 1536
__device__ float g_p2[BATCH * PRED * POSE];
__device__ float g_mem[BATCH * POSE];
__device__ float g_mem2[BATCH * POSE];
__device__ float g_s1[BATCH * CHUNK];
__device__ float g_penc[BATCH * CHUNK];
__device__ float g_t[POSE * CHUNK];

// ---------------- helpers ----------------
__device__ __forceinline__ uint32_t smem_u32(const void* p) {
    uint32_t a;
    asm("{ .reg .u64 t; cvta.to.shared.u64 t, %1; cvt.u32.u64 %0, t; }" : "=r"(a) : "l"(p));
    return a;
}
__device__ __forceinline__ void cp16(uint32_t dst, const void* src) {
    asm volatile("cp.async.cg.shared.global [%0], [%1], 16;" :: "r"(dst), "l"(src));
}

#define LDSM_X4(r0, r1, r2, r3, addr) \
    asm volatile("ldmatrix.sync.aligned.m8n8.x4.shared.b16 {%0, %1, %2, %3}, [%4];" \
        : "=r"(r0), "=r"(r1), "=r"(r2), "=r"(r3) : "r"(addr))

__device__ __forceinline__ void mma16816(float c[4], uint32_t a0, uint32_t a1, uint32_t a2, uint32_t a3,
                                         uint32_t b0, uint32_t b1) {
    asm volatile("mma.sync.aligned.m16n8k16.row.col.f32.f16.f16.f32 "
                 "{%0, %1, %2, %3}, {%4, %5, %6, %7}, {%8, %9}, {%0, %1, %2, %3};"
                 : "+f"(c[0]), "+f"(c[1]), "+f"(c[2]), "+f"(c[3])
                 : "r"(a0), "r"(a1), "r"(a2), "r"(a3), "r"(b0), "r"(b1));
}

__device__ __forceinline__ unsigned short f2h(float v) {
    __half h = __float2half_rn(v);
    return *(unsigned short*)&h;
}

// ---------------- HMMA fp16 single-pass NT GEMM, 128x128 tile, BK=64 (2-stage) ---------
// C[128x128 tile] = A[128 rows @ lda, K] @ B[128rows,K]^T
// CONVB=true : A = conv weights fp16 (lda=K), B = activations fp16 via shifted loader
// CONVB=false: A = activations fp16 (row stride lda), B = weights fp16 (row stride K)
// EPI 0: +bias(n) -> fp32 outf (ld ldc)
// EPI 1: +bias(n) -> fp16 outh (ld ldc)
// EPI 2: +convbias(m), relu, BN(m) -> transposed fp16 P1T[bz][h+1][och] (ld CIN2P)
// EPI 3: +convbias(m), relu, BN(m) -> fp32 p2[bz][och][h]; och>=CHUNK also fp16 -> outh
//        (outh = Ah concat buffer, row bz*FRAMES + PRIOR + och)
#define GBM 128
#define GBN 128
#define GBK 64
#define GLDS (GBK + 8)
#define GTILE (GBM * GLDS)                  // shorts per operand tile (9216)
#define GSTAGE_B (2 * GTILE * 2)            // bytes per stage (36864)
#define GSMEM_B (2 * GSTAGE_B)              // 73728

template <int EPI, bool CONVB>
__global__ __launch_bounds__(256, 2)
void mma_gemm(const unsigned short* __restrict__ A0, long lda,
              const unsigned short* __restrict__ B0,
              int K, int CINp, int ldc,
              const float* __restrict__ bias,
              const float* __restrict__ bng, const float* __restrict__ bnb,
              const float* __restrict__ bnm, const float* __restrict__ bnv,
              float* __restrict__ outf, unsigned short* __restrict__ outh)
{
    extern __shared__ unsigned short smraw[];
    const uint32_t u0 = smem_u32(smraw);

    const int tid = threadIdx.x;
    const int lane = tid & 31;
    const int w = tid >> 5;
    const int wm = w >> 2;          // 0..1 -> 64 rows each
    const int wn = w & 3;           // 0..3 -> 32 cols each
    const int m0 = blockIdx.y * GBM;
    const int n0 = blockIdx.x * GBN;
    const int bz = blockIdx.z;

    const int aRow = wm * 64 + (lane & 7) + ((lane >> 3) & 1) * 8;  // + mi*16
    const int aCol = ((lane >> 4) & 1) * 8;
    const int bRow = wn * 32 + (lane & 7) + ((lane >> 4) & 1) * 8;  // + nio*16
    const int bCol = ((lane >> 3) & 1) * 8;

    float c[4][4][4];
#pragma unroll
    for (int i = 0; i < 4; ++i)
#pragma unroll
        for (int j = 0; j < 4; ++j)
#pragma unroll
            for (int q = 0; q < 4; ++q) c[i][j][q] = 0.f;

    auto load_tile = [&](int kt, int s) {
        const int k0 = kt * GBK;
        int dlt = 0, i0 = k0;
        if (CONVB) { dlt = k0 / CINp; i0 = k0 - dlt * CINp; }
        const uint32_t sbase = u0 + (uint32_t)s * GSTAGE_B;
#pragma unroll
        for (int u = 0; u < 4; ++u) {       // A: 128 rows x 64 shorts = 1024 uint4
            const int idx = tid + u * 256;
            const int r = idx >> 3, cg = idx & 7;
            const uint32_t so = (uint32_t)((r * GLDS + cg * 8) * 2);
            const size_t ga = (size_t)(m0 + r) * lda + k0 + cg * 8;
            cp16(sbase + so, A0 + ga);
        }
#pragma unroll
        for (int u = 0; u < 4; ++u) {       // B: 128 rows x 64 shorts
            const int idx = tid + u * 256;
            const int r = idx >> 3, cg = idx & 7;
            const uint32_t so = (uint32_t)((r * GLDS + cg * 8) * 2);
            size_t gb;
            if (CONVB) gb = (size_t)((size_t)bz * XTR + n0 + r + dlt) * CINp + i0 + cg * 8;
            else       gb = (size_t)(n0 + r) * K + k0 + cg * 8;
            cp16(sbase + GTILE * 2 + so, B0 + gb);
        }
        asm volatile("cp.async.commit_group;" ::: "memory");
    };

    auto compute_tile = [&](int s) {
        const uint32_t t0 = u0 + (uint32_t)s * GSTAGE_B;
        const uint32_t t1 = t0 + GTILE * 2;
#pragma unroll
        for (int ks = 0; ks < 4; ++ks) {
            const int kk = ks * 16;
            uint32_t a[4][4];
#pragma unroll
            for (int mi = 0; mi < 4; ++mi) {
                uint32_t off = (uint32_t)(((aRow + mi * 16) * GLDS + kk + aCol) * 2);
                LDSM_X4(a[mi][0], a[mi][1], a[mi][2], a[mi][3], t0 + off);
            }
            uint32_t b[4][2];
#pragma unroll
            for (int nio = 0; nio < 2; ++nio) {
                uint32_t off = (uint32_t)(((bRow + nio * 16) * GLDS + kk + bCol) * 2);
                uint32_t r0, r1, r2, r3;
                LDSM_X4(r0, r1, r2, r3, t1 + off);
                b[nio * 2][0] = r0; b[nio * 2][1] = r1;
                b[nio * 2 + 1][0] = r2; b[nio * 2 + 1][1] = r3;
            }
#pragma unroll
            for (int mi = 0; mi < 4; ++mi)
#pragma unroll
                for (int ni = 0; ni < 4; ++ni)
                    mma16816(c[mi][ni], a[mi][0], a[mi][1], a[mi][2], a[mi][3],
                             b[ni][0], b[ni][1]);
        }
    };

    const int nkt = K / GBK;
    load_tile(0, 0);
    for (int kt = 0; kt < nkt; ++kt) {
        if (kt + 1 < nkt) {
            load_tile(kt + 1, (kt + 1) & 1);
            asm volatile("cp.async.wait_group 1;" ::: "memory");
        } else {
            asm volatile("cp.async.wait_group 0;" ::: "memory");
        }
        __syncthreads();
        compute_tile(kt & 1);
        __syncthreads();
    }

    // ---------------- epilogue from fragments ----------------
#pragma unroll
    for (int mi = 0; mi < 4; ++mi) {
#pragma unroll
        for (int ni = 0; ni < 4; ++ni) {
            const int col = n0 + wn * 32 + ni * 8 + (lane & 3) * 2;
#pragma unroll
            for (int half = 0; half < 2; ++half) {
                const int row = m0 + wm * 64 + mi * 16 + (lane >> 2) + half * 8;
                const float v0r = c[mi][ni][half * 2];
                const float v1r = c[mi][ni][half * 2 + 1];
                if (EPI == 0) {
                    float2 v;
                    v.x = v0r + bias[col];
                    v.y = v1r + bias[col + 1];
                    *(float2*)(outf + (size_t)row * ldc + col) = v;
                } else if (EPI == 1) {
                    unsigned int hv = (unsigned int)f2h(v0r + bias[col])
                                    | ((unsigned int)f2h(v1r + bias[col + 1]) << 16);
                    *(unsigned int*)(outh + (size_t)row * ldc + col) = hv;
                } else {
                    const int och = row;
                    if (och < PRED) {
                        const float cb = bias[och];
                        const float sc = bng[och] * rsqrtf(bnv[och] + EPS);
                        const float mo = bnm[och], bo = bnb[och];
                        float v0 = (fmaxf(v0r + cb, 0.f) - mo) * sc + bo;
                        float v1 = (fmaxf(v1r + cb, 0.f) - mo) * sc + bo;
                        if (EPI == 3) {
                            float2 v; v.x = v0; v.y = v1;
                            *(float2*)(outf + (size_t)((size_t)bz * PRED + och) * POSE + col) = v;
                            if (och >= CHUNK) {
                                unsigned int hv = (unsigned int)f2h(v0)
                                                | ((unsigned int)f2h(v1) << 16);
                                *(unsigned int*)(outh +
                                    (size_t)((size_t)bz * FRAMES + PRIOR + och) * POSE + col) = hv;
                            }
                        } else {
                            size_t oi0 = (size_t)((size_t)bz * XTR + col + 1) * CIN2P + och;
                            size_t oi1 = (size_t)((size_t)bz * XTR + col + 2) * CIN2P + och;
                            outh[oi0] = f2h(v0);
                            outh[oi1] = f2h(v1);
                        }
                    }
                }
            }
        }
    }
}

// ---------------- conversion kernels ----------------
__global__ void cvt_h(const float* __restrict__ s, unsigned short* __restrict__ h, int n)
{
    for (int i = blockIdx.x * blockDim.x + threadIdx.x; i < n; i += gridDim.x * blockDim.x)
        h[i] = f2h(s[i]);
}

// x rows: Ah rows 0..59 per batch
__global__ void cvt_xrows(const float* __restrict__ x, unsigned short* __restrict__ h)
{
    int m = blockIdx.x;
    int b = m / PRIOR, r = m - b * PRIOR;
    const float* src = x + ((size_t)b * PRIOR + r) * POSE;
    size_t dst = ((size_t)b * FRAMES + r) * POSE;
    for (int ci = threadIdx.x; ci < POSE; ci += 256)
        h[dst + ci] = f2h(src[ci]);
}

// gated chunk rows: Ah rows 60..69 per batch (after gates)
__global__ void cvt_chunk(const float* __restrict__ p2, unsigned short* __restrict__ h)
{
    int m = blockIdx.x;
    int b = m / CHUNK, r = m - b * CHUNK;
    const float* src = p2 + ((size_t)b * PRED + r) * POSE;
    size_t dst = ((size_t)b * FRAMES + PRIOR + r) * POSE;
    for (int ci = threadIdx.x; ci < POSE; ci += 256)
        h[dst + ci] = f2h(src[ci]);
}

__global__ void cvt_convw(const float* __restrict__ wsrc, unsigned short* __restrict__ h,
                          int CIN, int CINp)
{
    int total = PRED * CIN * 3;
    int KC = 3 * CINp;
    for (int idx = blockIdx.x * blockDim.x + threadIdx.x; idx < total; idx += gridDim.x * blockDim.x) {
        int o = idx / (CIN * 3);
        int rem = idx - o * (CIN * 3);
        int i = rem / 3, d = rem - i * 3;
        h[(size_t)o * KC + (size_t)d * CINp + i] = f2h(wsrc[idx]);
    }
}

__global__ void cvt_xT(const float* __restrict__ x, unsigned short* __restrict__ h)
{
    __shared__ float t[64][65];
    int b = blockIdx.y, h0 = blockIdx.x * 64;
    for (int idx = threadIdx.x; idx < PRIOR * 64; idx += 256) {
        int i = idx >> 6, hh = idx & 63;
        t[hh][i] = x[((size_t)b * PRIOR + i) * POSE + h0 + hh];
    }
    __syncthreads();
    for (int idx = threadIdx.x; idx < 64 * PRIOR; idx += 256) {
        int hh = idx / PRIOR, i = idx - hh * PRIOR;
        h[((size_t)b * XTR + h0 + hh + 1) * CIN1P + i] = f2h(t[hh][i]);
    }
}

// ---------------- FFMA NT GEMM (tmm encoder only) ----------------
template <int BM, int BN, int BK, int TM, int TN>
__global__ __launch_bounds__((BM / TM) * (BN / TN))
void sgemm_nt(const float* __restrict__ A, long lda,
              const float* __restrict__ W,
              const float* __restrict__ bias,
              float* __restrict__ C, int ldc,
              int M, int N, int K)
{
    constexpr int THREADS = (BM / TM) * (BN / TN);
    constexpr int ASLOTS = BM * BK / THREADS;
    constexpr int BSLOTS = BN * BK / THREADS;
    __shared__ float As[BK][BM + 4];
    __shared__ float Bs[BK][BN + 4];
    const int tid = threadIdx.x;
    const int bm = blockIdx.y * BM;
    const int bn = blockIdx.x * BN;
    const int tx = tid % (BN / TN);
    const int ty = tid / (BN / TN);

    float acc[TM][TN];
#pragma unroll
    for (int i = 0; i < TM; ++i)
#pragma unroll
        for (int j = 0; j < TN; ++j) acc[i][j] = 0.f;

    for (int k0 = 0; k0 < K; k0 += BK) {
#pragma unroll
        for (int j = 0; j < ASLOTS; ++j) {
            int s = tid + j * THREADS;
            int kl = s % BK, ml = s / BK;
            int k = k0 + kl, m = bm + ml;
            As[kl][ml] = (k < K && m < M) ? A[(long)m * lda + k] : 0.f;
        }
#pragma unroll
        for (int j = 0; j < BSLOTS; ++j) {
            int s = tid + j * THREADS;
            int kl = s % BK, nl = s / BK;
            int k = k0 + kl, n = bn + nl;
            Bs[kl][nl] = (k < K && n < N) ? W[(long)n * K + k] : 0.f;
        }
        __syncthreads();
#pragma unroll
        for (int kk = 0; kk < BK; ++kk) {
            float a[TM], b[TN];
#pragma unroll
            for (int i = 0; i < TM; ++i) a[i] = As[kk][ty * TM + i];
#pragma unroll
            for (int j = 0; j < TN; ++j) b[j] = Bs[kk][tx * TN + j];
#pragma unroll
            for (int i = 0; i < TM; ++i)
#pragma unroll
                for (int j = 0; j < TN; ++j) acc[i][j] += a[i] * b[j];
        }
        __syncthreads();
    }
#pragma unroll
    for (int i = 0; i < TM; ++i) {
        int m = bm + ty * TM + i;
        if (m >= M) continue;
#pragma unroll
        for (int j = 0; j < TN; ++j) {
            int n = bn + tx * TN + j;
            if (n < N) C[(long)m * ldc + n] = acc[i][j] + bias[n];
        }
    }
}

// ---------------- gate kernels ----------------
__global__ void sp_gate_kernel(const float* __restrict__ mem, float* __restrict__ p)
{
    int b = blockIdx.x;
    int tid = threadIdx.x;
    int w = tid >> 5, lane = tid & 31;
    __shared__ float sig_s[CHUNK];
    const float* pm = mem + (long)b * POSE;
    const float* pc = p + (long)b * PRED * POSE + (long)w * POSE;
    float s = 0.f;
    for (int d = lane; d < POSE; d += 32) s += pm[d] * pc[d];
#pragma unroll
    for (int o = 16; o; o >>= 1) s += __shfl_xor_sync(0xffffffffu, s, o);
    if (lane == 0) sig_s[w] = 1.f / (1.f + expf(-s));
    __syncthreads();
    float* pb = p + (long)b * PRED * POSE;
    for (int idx = tid; idx < CHUNK * POSE; idx += 320) {
        int cc = idx / POSE, d = idx - cc * POSE;
        float g = sig_s[cc];
        pb[idx] = g * pb[idx] + (1.f - g) * pm[d];
    }
}

__global__ void tm_t_kernel(const float* __restrict__ mem2, const float* __restrict__ penc,
                            float* __restrict__ t)
{
    int d = blockIdx.x;
    int tid = threadIdx.x;
    float acc[CHUNK];
#pragma unroll
    for (int cc = 0; cc < CHUNK; ++cc) acc[cc] = 0.f;
    for (int b = tid; b < BATCH; b += 64) {
        float m = mem2[(long)b * POSE + d];
        const float* pr = penc + (long)b * CHUNK;
#pragma unroll
        for (int cc = 0; cc < CHUNK; ++cc) acc[cc] += m * pr[cc];
    }
    __shared__ float red[64][CHUNK];
#pragma unroll
    for (int cc = 0; cc < CHUNK; ++cc) red[tid][cc] = acc[cc];
    __syncthreads();
    for (int off = 32; off >= 1; off >>= 1) {
        if (tid < off)
#pragma unroll
            for (int cc = 0; cc < CHUNK; ++cc) red[tid][cc] += red[tid + off][cc];
        __syncthreads();
    }
    if (tid == 0)
#pragma unroll
        for (int cc = 0; cc < CHUNK; ++cc) t[(long)d * CHUNK + cc] = red[0][cc];
}

__global__ void tm_apply_kernel(const float* __restrict__ mem2, const float* __restrict__ t,
                                float* __restrict__ p)
{
    int b = blockIdx.x;
    int tid = threadIdx.x;
    float acc[CHUNK];
#pragma unroll
    for (int cc = 0; cc < CHUNK; ++cc) acc[cc] = 0.f;
    const float* mb = mem2 + (long)b * POSE;
    for (int d = tid; d < POSE; d += 256) {
        float m = mb[d];
        const float* tr = t + (long)d * CHUNK;
#pragma unroll
        for (int cc = 0; cc < CHUNK; ++cc) acc[cc] += m * tr[cc];
    }
    __shared__ float red[256][CHUNK];
    __shared__ float soft[CHUNK];
#pragma unroll
    for (int cc = 0; cc < CHUNK; ++cc) red[tid][cc] = acc[cc];
    __syncthreads();
    for (int off = 128; off >= 1; off >>= 1) {
        if (tid < off)
#pragma unroll
            for (int cc = 0; cc < CHUNK; ++cc) red[tid][cc] += red[tid + off][cc];
        __syncthreads();
    }
    if (tid == 0) {
        float mx = red[0][0];
#pragma unroll
        for (int cc = 1; cc < CHUNK; ++cc) mx = fmaxf(mx, red[0][cc]);
        float sum = 0.f, e[CHUNK];
#pragma unroll
        for (int cc = 0; cc < CHUNK; ++cc) { e[cc] = expf(red[0][cc] - mx); sum += e[cc]; }
        float inv = 1.f / sum;
#pragma unroll
        for (int cc = 0; cc < CHUNK; ++cc) soft[cc] = e[cc] * inv;
    }
    __syncthreads();
    float* pb = p + (long)b * PRED * POSE;
    for (int idx = tid; idx < CHUNK * POSE; idx += 256) {
        int cc = idx / POSE;
        pb[idx] *= (1.f + soft[cc]);
    }
}

// ---------------- host launcher ----------------
extern "C" void kernel_launch(void* const* d_in, const int* in_sizes, int n_in,
                              void* d_out, int out_size)
{
    (void)in_sizes; (void)n_in; (void)out_size;
    const float* x       = (const float*)d_in[0];
    const float* conv1_w = (const float*)d_in[1];
    const float* conv1_b = (const float*)d_in[2];
    const float* bn1_g   = (const float*)d_in[3];
    const float* bn1_b   = (const float*)d_in[4];
    const float* bn1_m   = (const float*)d_in[5];
    const float* bn1_v   = (const float*)d_in[6];
    const float* conv2_w = (const float*)d_in[7];
    const float* conv2_b = (const float*)d_in[8];
    const float* bn2_g   = (const float*)d_in[9];
    const float* bn2_b   = (const float*)d_in[10];
    const float* bn2_m   = (const float*)d_in[11];
    const float* bn2_v   = (const float*)d_in[12];
    const float* sp_w1   = (const float*)d_in[13];
    const float* sp_b1   = (const float*)d_in[14];
    const float* sp_w2   = (const float*)d_in[15];
    const float* sp_b2   = (const float*)d_in[16];
    const float* tmc_w1  = (const float*)d_in[17];
    const float* tmc_b1  = (const float*)d_in[18];
    const float* tmc_w2  = (const float*)d_in[19];
    const float* tmc_b2  = (const float*)d_in[20];
    const float* tmm_w1  = (const float*)d_in[21];
    const float* tmm_b1  = (const float*)d_in[22];
    const float* tmm_w2  = (const float*)d_in[23];
    const float* tmm_b2  = (const float*)d_in[24];
    const float* post_w1 = (const float*)d_in[25];
    const float* post_b1 = (const float*)d_in[26];
    const float* post_w2 = (const float*)d_in[27];
    const float* post_b2 = (const float*)d_in[28];

    unsigned short *Ah, *Hh, *W1h, *W2h, *Xth, *P1h, *Wc1h, *Wc2h;
    unsigned short *Wm, *W2sh, *W2th, *tmph;
    float *bm, *p2, *mem, *mem2, *s1, *penc, *t;
    cudaGetSymbolAddress((void**)&Ah, g_Ah);
    cudaGetSymbolAddress((void**)&Hh, g_Hh);
    cudaGetSymbolAddress((void**)&W1h, g_W1h);
    cudaGetSymbolAddress((void**)&W2h, g_W2h);
    cudaGetSymbolAddress((void**)&Xth, g_Xth);
    cudaGetSymbolAddress((void**)&P1h, g_P1h);
    cudaGetSymbolAddress((void**)&Wc1h, g_Wc1h);
    cudaGetSymbolAddress((void**)&Wc2h, g_Wc2h);
    cudaGetSymbolAddress((void**)&Wm, g_Wm);
    cudaGetSymbolAddress((void**)&bm, g_bm);
    cudaGetSymbolAddress((void**)&W2sh, g_W2sh);
    cudaGetSymbolAddress((void**)&W2th, g_W2th);
    cudaGetSymbolAddress((void**)&tmph, g_tmph);
    cudaGetSymbolAddress((void**)&p2, g_p2);
    cudaGetSymbolAddress((void**)&mem, g_mem);
    cudaGetSymbolAddress((void**)&mem2, g_mem2);
    cudaGetSymbolAddress((void**)&s1, g_s1);
    cudaGetSymbolAddress((void**)&penc, g_penc);
    cudaGetSymbolAddress((void**)&t, g_t);

    cudaFuncSetAttribute(mma_gemm<0, false>, cudaFuncAttributeMaxDynamicSharedMemorySize, GSMEM_B);
    cudaFuncSetAttribute(mma_gemm<1, false>, cudaFuncAttributeMaxDynamicSharedMemorySize, GSMEM_B);
    cudaFuncSetAttribute(mma_gemm<2, true>,  cudaFuncAttributeMaxDynamicSharedMemorySize, GSMEM_B);
    cudaFuncSetAttribute(mma_gemm<3, true>,  cudaFuncAttributeMaxDynamicSharedMemorySize, GSMEM_B);

    // launches 0-4: conv1 dependencies + filler conversions (so launch 5 = conv1 mma_gemm,
    // which is what ncu's "-s 5 -c 1" captures)
    cvt_convw<<<128, 256>>>(conv1_w, Wc1h, PRIOR, CIN1P);        // 0
    cvt_xT<<<dim3(POSE / 64, BATCH), 256>>>(x, Xth);             // 1
    cvt_h<<<512, 256>>>(post_w1, W1h, POSE * POSE);              // 2
    cvt_h<<<512, 256>>>(post_w2, W2h, POSE * POSE);              // 3
    cvt_convw<<<256, 256>>>(conv2_w, Wc2h, PRED, CIN2P);         // 4

    // 5: conv1 (captured by ncu): W[180(pad256),192] @ XT^T -> P1T fp16
    mma_gemm<2, true><<<dim3(POSE / GBN, 2, BATCH), 256, GSMEM_B>>>(
        Wc1h, KC1, Xth, KC1, CIN1P, 0,
        conv1_b, bn1_g, bn1_b, bn1_m, bn1_v, nullptr, P1h);

    // remaining conversions (independent of conv pipeline)
    cvt_h<<<512, 256>>>(sp_w1,  Wm,                        POSE * KENC);
    cvt_h<<<512, 256>>>(tmc_w1, Wm + (size_t)POSE * KENC, POSE * KENC);
    cvt_h<<<64, 256>>>(sp_w2,  W2sh, POSE * POSE);
    cvt_h<<<64, 256>>>(tmc_w2, W2th, POSE * POSE);
    cudaMemcpyAsync(bm, sp_b1, POSE * sizeof(float), cudaMemcpyDeviceToDevice);
    cudaMemcpyAsync(bm + POSE, tmc_b1, POSE * sizeof(float), cudaMemcpyDeviceToDevice);
    cvt_xrows<<<BATCH * PRIOR, 256>>>(x, Ah);

    // conv2: W[180(pad256),576] @ P1T^T -> p2 fp32 + Ah fp16 rows (frames >= CHUNK)
    mma_gemm<3, true><<<dim3(POSE / GBN, 2, BATCH), 256, GSMEM_B>>>(
        Wc2h, KC2, P1h, KC2, CIN2P, 0,
        conv2_b, bn2_g, bn2_b, bn2_m, bn2_v, p2, Ah);

    // encoder layer-1 on HMMA: A = tail rows of Ah (frames 50..59), B = Wm [1536,7680]
    mma_gemm<1, false><<<dim3(2 * POSE / GBN, BATCH / GBM), 256, GSMEM_B>>>(
        Ah + (size_t)(PRIOR - CHUNK) * POSE, (long)FRAMES * POSE, Wm, KENC, 0, 2 * POSE,
        bm, nullptr, nullptr, nullptr, nullptr, nullptr, tmph);
    // encoder layer-2 on HMMA: mem / mem2 fp32
    mma_gemm<0, false><<<dim3(POSE / GBN, BATCH / GBM), 256, GSMEM_B>>>(
        tmph, 2 * POSE, W2sh, POSE, 0, POSE,
        sp_b2, nullptr, nullptr, nullptr, nullptr, mem, nullptr);
    mma_gemm<0, false><<<dim3(POSE / GBN, BATCH / GBM), 256, GSMEM_B>>>(
        tmph + POSE, 2 * POSE, W2th, POSE, 0, POSE,
        tmc_b2, nullptr, nullptr, nullptr, nullptr, mem2, nullptr);

    // gates + tmm encoder (FFMA, tiny)
    sp_gate_kernel<<<BATCH, CHUNK * 32>>>(mem, p2);
    sgemm_nt<32, 128, 16, 4, 8><<<dim3(1, BATCH / 32), 128>>>(
        p2, (long)PRED * POSE, tmm_w1, tmm_b1, s1, CHUNK, BATCH, CHUNK, KENC);
    sgemm_nt<32, 128, 16, 4, 8><<<dim3(1, BATCH / 32), 128>>>(
        s1, CHUNK, tmm_w2, tmm_b2, penc, CHUNK, BATCH, CHUNK, CHUNK);
    tm_t_kernel<<<POSE, 64>>>(mem2, penc, t);
    tm_apply_kernel<<<BATCH, 256>>>(mem2, t, p2);

    // fill Ah gated chunk rows 60..69 per batch
    cvt_chunk<<<BATCH * CHUNK, 256>>>(p2, Ah);

    // post header on HMMA tensor path (single-pass fp16)
    mma_gemm<1, false><<<dim3(POSE / GBN, MROWS / 128), 256, GSMEM_B>>>(
        Ah, POSE, W1h, POSE, 0, POSE,
        post_b1, nullptr, nullptr, nullptr, nullptr, nullptr, Hh);
    mma_gemm<0, false><<<dim3(POSE / GBN, MROWS / 128), 256, GSMEM_B>>>(
        Hh, POSE, W2h, POSE, 0, POSE,
        post_b2, nullptr, nullptr, nullptr, nullptr, (float*)d_out, nullptr);
}

// round 17
// speedup vs baseline: 1.0512x; 1.0512x over previous
#include <cuda_runtime.h>
#include <cuda_fp16.h>
#include <math.h>
#include <stdint.h>

#define BATCH  256
#define PRIOR  60
#define FRAMES 240
#define POSE   768
#define CHUNK  10
#define PRED   180
#define EPS    1e-5f
#define MROWS  (BATCH * FRAMES)
#define CIN1P  64
#define CIN2P  192
#define KC1    (3 * CIN1P)
#define KC2    (3 * CIN2P)
#define XTR    770
#define KENC   (CHUNK * POSE)      // 7680

// ---------------- scratch (zero-initialized device globals; padding rows/channels are
// never written by any kernel, so they stay zero forever -> deterministic) -------------
__device__ unsigned short g_Ah[MROWS * POSE];                 // concat rows, fp16
__device__ unsigned short g_Hh[MROWS * POSE];                 // h1, fp16
__device__ unsigned short g_W1h[POSE * POSE];
__device__ unsigned short g_W2h[POSE * POSE];
__device__ unsigned short g_Xth[BATCH * XTR * CIN1P];         // xT padded, fp16
__device__ unsigned short g_P1h[BATCH * XTR * CIN2P];         // conv1 out (transposed), fp16
__device__ unsigned short g_Wc1h[256 * KC1];
__device__ unsigned short g_Wc2h[256 * KC2];
__device__ unsigned short g_Wm[2 * POSE * KENC];              // sp_w1 | tmc_w1 fp16
__device__ float          g_bm[2 * POSE];                     // sp_b1 | tmc_b1
__device__ unsigned short g_W2sh[POSE * POSE];                // sp_w2 fp16
__device__ unsigned short g_W2th[POSE * POSE];                // tmc_w2 fp16
__device__ unsigned short g_tmph[BATCH * 2 * POSE];           // enc layer-1 out fp16, ld 1536
__device__ float g_p2[BATCH * PRED * POSE];
__device__ float g_mem[BATCH * POSE];
__device__ float g_mem2[BATCH * POSE];
__device__ float g_s1[BATCH * CHUNK];
__device__ float g_penc[BATCH * CHUNK];
__device__ float g_t[POSE * CHUNK];

// ---------------- helpers ----------------
__device__ __forceinline__ uint32_t smem_u32(const void* p) {
    uint32_t a;
    asm("{ .reg .u64 t; cvta.to.shared.u64 t, %1; cvt.u32.u64 %0, t; }" : "=r"(a) : "l"(p));
    return a;
}
__device__ __forceinline__ void cp16(uint32_t dst, const void* src) {
    asm volatile("cp.async.cg.shared.global [%0], [%1], 16;" :: "r"(dst), "l"(src));
}

#define LDSM_X4(r0, r1, r2, r3, addr) \
    asm volatile("ldmatrix.sync.aligned.m8n8.x4.shared.b16 {%0, %1, %2, %3}, [%4];" \
        : "=r"(r0), "=r"(r1), "=r"(r2), "=r"(r3) : "r"(addr))

__device__ __forceinline__ void mma16816(float c[4], uint32_t a0, uint32_t a1, uint32_t a2, uint32_t a3,
                                         uint32_t b0, uint32_t b1) {
    asm volatile("mma.sync.aligned.m16n8k16.row.col.f32.f16.f16.f32 "
                 "{%0, %1, %2, %3}, {%4, %5, %6, %7}, {%8, %9}, {%0, %1, %2, %3};"
                 : "+f"(c[0]), "+f"(c[1]), "+f"(c[2]), "+f"(c[3])
                 : "r"(a0), "r"(a1), "r"(a2), "r"(a3), "r"(b0), "r"(b1));
}

__device__ __forceinline__ unsigned short f2h(float v) {
    __half h = __float2half_rn(v);
    return *(unsigned short*)&h;
}

// ---------------- HMMA fp16 single-pass NT GEMM, {128|64}x128 tile, BK=64 (2-stage) ----
// C[MT x 128 tile] = A[MT rows @ lda, K] @ B[128rows,K]^T      (rows offset by moff)
// CONVB=true : A = conv weights fp16 (lda=K), B = activations fp16 via shifted loader
// CONVB=false: A = activations fp16 (row stride lda), B = weights fp16 (row stride K)
// EPI 0: +bias(n) -> fp32 outf (ld ldc)
// EPI 1: +bias(n) -> fp16 outh (ld ldc)
// EPI 2: +convbias(m), relu, BN(m) -> transposed fp16 P1T[bz][h+1][och] (ld CIN2P)
// EPI 3: +convbias(m), relu, BN(m) -> fp32 p2[bz][och][h]; och>=CHUNK also fp16 -> outh
//        (outh = Ah concat buffer, row bz*FRAMES + PRIOR + och)
#define GBN 128
#define GBK 64
#define GLDS (GBK + 8)
#define GTILE (128 * GLDS)                  // shorts per operand tile slot (9216)
#define GSTAGE_B (2 * GTILE * 2)            // bytes per stage (36864)
#define GSMEM_B (2 * GSTAGE_B)              // 73728

template <int EPI, bool CONVB, int MT>
__global__ __launch_bounds__(256)
void mma_gemm(const unsigned short* __restrict__ A0, long lda, int moff,
              const unsigned short* __restrict__ B0,
              int K, int CINp, int ldc,
              const float* __restrict__ bias,
              const float* __restrict__ bng, const float* __restrict__ bnb,
              const float* __restrict__ bnm, const float* __restrict__ bnv,
              float* __restrict__ outf, unsigned short* __restrict__ outh)
{
    constexpr int NCW = (MT == 128) ? 32 : 16;   // cols per warp
    constexpr int NIO = NCW / 16;                // B ldmatrix groups per warp (2 or 1)
    constexpr int NF = 2 * NIO;                  // B n-fragments per warp (4 or 2)

    extern __shared__ unsigned short smraw[];
    const uint32_t u0 = smem_u32(smraw);

    const int tid = threadIdx.x;
    const int lane = tid & 31;
    const int w = tid >> 5;
    const int wm = (MT == 128) ? (w >> 2) : 0;
    const int wn = (MT == 128) ? (w & 3) : w;
    const int m0 = moff + blockIdx.y * MT;
    const int n0 = blockIdx.x * GBN;
    const int bz = blockIdx.z;

    const int aRow = wm * 64 + (lane & 7) + ((lane >> 3) & 1) * 8;  // + mi*16
    const int aCol = ((lane >> 4) & 1) * 8;
    const int bRow = wn * NCW + (lane & 7) + ((lane >> 4) & 1) * 8; // + nio*16
    const int bCol = ((lane >> 3) & 1) * 8;

    float c[4][NF][4];
#pragma unroll
    for (int i = 0; i < 4; ++i)
#pragma unroll
        for (int j = 0; j < NF; ++j)
#pragma unroll
            for (int q = 0; q < 4; ++q) c[i][j][q] = 0.f;

    auto load_tile = [&](int kt, int s) {
        const int k0 = kt * GBK;
        int dlt = 0, i0 = k0;
        if (CONVB) { dlt = k0 / CINp; i0 = k0 - dlt * CINp; }
        const uint32_t sbase = u0 + (uint32_t)s * GSTAGE_B;
#pragma unroll
        for (int u = 0; u < MT / 32; ++u) {  // A: MT rows x 64 shorts
            const int idx = tid + u * 256;
            const int r = idx >> 3, cg = idx & 7;
            const uint32_t so = (uint32_t)((r * GLDS + cg * 8) * 2);
            const size_t ga = (size_t)(m0 + r) * lda + k0 + cg * 8;
            cp16(sbase + so, A0 + ga);
        }
#pragma unroll
        for (int u = 0; u < 4; ++u) {        // B: 128 rows x 64 shorts
            const int idx = tid + u * 256;
            const int r = idx >> 3, cg = idx & 7;
            const uint32_t so = (uint32_t)((r * GLDS + cg * 8) * 2);
            size_t gb;
            if (CONVB) gb = (size_t)((size_t)bz * XTR + n0 + r + dlt) * CINp + i0 + cg * 8;
            else       gb = (size_t)(n0 + r) * K + k0 + cg * 8;
            cp16(sbase + GTILE * 2 + so, B0 + gb);
        }
        asm volatile("cp.async.commit_group;" ::: "memory");
    };

    auto compute_tile = [&](int s) {
        const uint32_t t0 = u0 + (uint32_t)s * GSTAGE_B;
        const uint32_t t1 = t0 + GTILE * 2;
#pragma unroll
        for (int ks = 0; ks < 4; ++ks) {
            const int kk = ks * 16;
            uint32_t a[4][4];
#pragma unroll
            for (int mi = 0; mi < 4; ++mi) {
                uint32_t off = (uint32_t)(((aRow + mi * 16) * GLDS + kk + aCol) * 2);
                LDSM_X4(a[mi][0], a[mi][1], a[mi][2], a[mi][3], t0 + off);
            }
            uint32_t b[NF][2];
#pragma unroll
            for (int nio = 0; nio < NIO; ++nio) {
                uint32_t off = (uint32_t)(((bRow + nio * 16) * GLDS + kk + bCol) * 2);
                uint32_t r0, r1, r2, r3;
                LDSM_X4(r0, r1, r2, r3, t1 + off);
                b[nio * 2][0] = r0; b[nio * 2][1] = r1;
                b[nio * 2 + 1][0] = r2; b[nio * 2 + 1][1] = r3;
            }
#pragma unroll
            for (int mi = 0; mi < 4; ++mi)
#pragma unroll
                for (int ni = 0; ni < NF; ++ni)
                    mma16816(c[mi][ni], a[mi][0], a[mi][1], a[mi][2], a[mi][3],
                             b[ni][0], b[ni][1]);
        }
    };

    const int nkt = K / GBK;
    load_tile(0, 0);
    for (int kt = 0; kt < nkt; ++kt) {
        if (kt + 1 < nkt) {
            load_tile(kt + 1, (kt + 1) & 1);
            asm volatile("cp.async.wait_group 1;" ::: "memory");
        } else {
            asm volatile("cp.async.wait_group 0;" ::: "memory");
        }
        __syncthreads();
        compute_tile(kt & 1);
        __syncthreads();
    }

    // ---------------- epilogue from fragments ----------------
#pragma unroll
    for (int mi = 0; mi < 4; ++mi) {
#pragma unroll
        for (int ni = 0; ni < NF; ++ni) {
            const int col = n0 + wn * NCW + ni * 8 + (lane & 3) * 2;
#pragma unroll
            for (int half = 0; half < 2; ++half) {
                const int row = m0 + wm * 64 + mi * 16 + (lane >> 2) + half * 8;
                const float v0r = c[mi][ni][half * 2];
                const float v1r = c[mi][ni][half * 2 + 1];
                if (EPI == 0) {
                    float2 v;
                    v.x = v0r + bias[col];
                    v.y = v1r + bias[col + 1];
                    *(float2*)(outf + (size_t)row * ldc + col) = v;
                } else if (EPI == 1) {
                    unsigned int hv = (unsigned int)f2h(v0r + bias[col])
                                    | ((unsigned int)f2h(v1r + bias[col + 1]) << 16);
                    *(unsigned int*)(outh + (size_t)row * ldc + col) = hv;
                } else {
                    const int och = row;
                    if (och < PRED) {
                        const float cb = bias[och];
                        const float sc = bng[och] * rsqrtf(bnv[och] + EPS);
                        const float mo = bnm[och], bo = bnb[och];
                        float v0 = (fmaxf(v0r + cb, 0.f) - mo) * sc + bo;
                        float v1 = (fmaxf(v1r + cb, 0.f) - mo) * sc + bo;
                        if (EPI == 3) {
                            float2 v; v.x = v0; v.y = v1;
                            *(float2*)(outf + (size_t)((size_t)bz * PRED + och) * POSE + col) = v;
                            if (och >= CHUNK) {
                                unsigned int hv = (unsigned int)f2h(v0)
                                                | ((unsigned int)f2h(v1) << 16);
                                *(unsigned int*)(outh +
                                    (size_t)((size_t)bz * FRAMES + PRIOR + och) * POSE + col) = hv;
                            }
                        } else {
                            size_t oi0 = (size_t)((size_t)bz * XTR + col + 1) * CIN2P + och;
                            size_t oi1 = (size_t)((size_t)bz * XTR + col + 2) * CIN2P + och;
                            outh[oi0] = f2h(v0);
                            outh[oi1] = f2h(v1);
                        }
                    }
                }
            }
        }
    }
}

// ---------------- conversion kernels ----------------
__global__ void cvt_h4(const float4* __restrict__ s, ushort4* __restrict__ h, int n4)
{
    for (int i = blockIdx.x * blockDim.x + threadIdx.x; i < n4; i += gridDim.x * blockDim.x) {
        float4 v = s[i];
        ushort4 o;
        o.x = f2h(v.x); o.y = f2h(v.y); o.z = f2h(v.z); o.w = f2h(v.w);
        h[i] = o;
    }
}

// x rows: Ah rows 0..59 per batch
__global__ void cvt_xrows(const float* __restrict__ x, unsigned short* __restrict__ h)
{
    int m = blockIdx.x;
    int b = m / PRIOR, r = m - b * PRIOR;
    const float* src = x + ((size_t)b * PRIOR + r) * POSE;
    size_t dst = ((size_t)b * FRAMES + r) * POSE;
    for (int ci = threadIdx.x; ci < POSE; ci += 256)
        h[dst + ci] = f2h(src[ci]);
}

// gated chunk rows: Ah rows 60..69 per batch (after gates)
__global__ void cvt_chunk(const float* __restrict__ p2, unsigned short* __restrict__ h)
{
    int m = blockIdx.x;
    int b = m / CHUNK, r = m - b * CHUNK;
    const float* src = p2 + ((size_t)b * PRED + r) * POSE;
    size_t dst = ((size_t)b * FRAMES + PRIOR + r) * POSE;
    for (int ci = threadIdx.x; ci < POSE; ci += 256)
        h[dst + ci] = f2h(src[ci]);
}

__global__ void cvt_convw(const float* __restrict__ wsrc, unsigned short* __restrict__ h,
                          int CIN, int CINp)
{
    int total = PRED * CIN * 3;
    int KC = 3 * CINp;
    for (int idx = blockIdx.x * blockDim.x + threadIdx.x; idx < total; idx += gridDim.x * blockDim.x) {
        int o = idx / (CIN * 3);
        int rem = idx - o * (CIN * 3);
        int i = rem / 3, d = rem - i * 3;
        h[(size_t)o * KC + (size_t)d * CINp + i] = f2h(wsrc[idx]);
    }
}

__global__ void cvt_xT(const float* __restrict__ x, unsigned short* __restrict__ h)
{
    __shared__ float t[64][65];
    int b = blockIdx.y, h0 = blockIdx.x * 64;
    for (int idx = threadIdx.x; idx < PRIOR * 64; idx += 256) {
        int i = idx >> 6, hh = idx & 63;
        t[hh][i] = x[((size_t)b * PRIOR + i) * POSE + h0 + hh];
    }
    __syncthreads();
    for (int idx = threadIdx.x; idx < 64 * PRIOR; idx += 256) {
        int hh = idx / PRIOR, i = idx - hh * PRIOR;
        h[((size_t)b * XTR + h0 + hh + 1) * CIN1P + i] = f2h(t[hh][i]);
    }
}

// ---------------- FFMA NT GEMM (tmm encoder only) ----------------
template <int BM, int BN, int BK, int TM, int TN>
__global__ __launch_bounds__((BM / TM) * (BN / TN))
void sgemm_nt(const float* __restrict__ A, long lda,
              const float* __restrict__ W,
              const float* __restrict__ bias,
              float* __restrict__ C, int ldc,
              int M, int N, int K)
{
    constexpr int THREADS = (BM / TM) * (BN / TN);
    constexpr int ASLOTS = BM * BK / THREADS;
    constexpr int BSLOTS = BN * BK / THREADS;
    __shared__ float As[BK][BM + 4];
    __shared__ float Bs[BK][BN + 4];
    const int tid = threadIdx.x;
    const int bm = blockIdx.y * BM;
    const int bn = blockIdx.x * BN;
    const int tx = tid % (BN / TN);
    const int ty = tid / (BN / TN);

    float acc[TM][TN];
#pragma unroll
    for (int i = 0; i < TM; ++i)
#pragma unroll
        for (int j = 0; j < TN; ++j) acc[i][j] = 0.f;

    for (int k0 = 0; k0 < K; k0 += BK) {
#pragma unroll
        for (int j = 0; j < ASLOTS; ++j) {
            int s = tid + j * THREADS;
            int kl = s % BK, ml = s / BK;
            int k = k0 + kl, m = bm + ml;
            As[kl][ml] = (k < K && m < M) ? A[(long)m * lda + k] : 0.f;
        }
#pragma unroll
        for (int j = 0; j < BSLOTS; ++j) {
            int s = tid + j * THREADS;
            int kl = s % BK, nl = s / BK;
            int k = k0 + kl, n = bn + nl;
            Bs[kl][nl] = (k < K && n < N) ? W[(long)n * K + k] : 0.f;
        }
        __syncthreads();
#pragma unroll
        for (int kk = 0; kk < BK; ++kk) {
            float a[TM], b[TN];
#pragma unroll
            for (int i = 0; i < TM; ++i) a[i] = As[kk][ty * TM + i];
#pragma unroll
            for (int j = 0; j < TN; ++j) b[j] = Bs[kk][tx * TN + j];
#pragma unroll
            for (int i = 0; i < TM; ++i)
#pragma unroll
                for (int j = 0; j < TN; ++j) acc[i][j] += a[i] * b[j];
        }
        __syncthreads();
    }
#pragma unroll
    for (int i = 0; i < TM; ++i) {
        int m = bm + ty * TM + i;
        if (m >= M) continue;
#pragma unroll
        for (int j = 0; j < TN; ++j) {
            int n = bn + tx * TN + j;
            if (n < N) C[(long)m * ldc + n] = acc[i][j] + bias[n];
        }
    }
}

// ---------------- gate kernels ----------------
__global__ void sp_gate_kernel(const float* __restrict__ mem, float* __restrict__ p)
{
    int b = blockIdx.x;
    int tid = threadIdx.x;
    int w = tid >> 5, lane = tid & 31;
    __shared__ float sig_s[CHUNK];
    const float* pm = mem + (long)b * POSE;
    const float* pc = p + (long)b * PRED * POSE + (long)w * POSE;
    float s = 0.f;
    for (int d = lane; d < POSE; d += 32) s += pm[d] * pc[d];
#pragma unroll
    for (int o = 16; o; o >>= 1) s += __shfl_xor_sync(0xffffffffu, s, o);
    if (lane == 0) sig_s[w] = 1.f / (1.f + expf(-s));
    __syncthreads();
    float* pb = p + (long)b * PRED * POSE;
    for (int idx = tid; idx < CHUNK * POSE; idx += 320) {
        int cc = idx / POSE, d = idx - cc * POSE;
        float g = sig_s[cc];
        pb[idx] = g * pb[idx] + (1.f - g) * pm[d];
    }
}

__global__ void tm_t_kernel(const float* __restrict__ mem2, const float* __restrict__ penc,
                            float* __restrict__ t)
{
    int d = blockIdx.x;
    int tid = threadIdx.x;
    float acc[CHUNK];
#pragma unroll
    for (int cc = 0; cc < CHUNK; ++cc) acc[cc] = 0.f;
    for (int b = tid; b < BATCH; b += 64) {
        float m = mem2[(long)b * POSE + d];
        const float* pr = penc + (long)b * CHUNK;
#pragma unroll
        for (int cc = 0; cc < CHUNK; ++cc) acc[cc] += m * pr[cc];
    }
    __shared__ float red[64][CHUNK];
#pragma unroll
    for (int cc = 0; cc < CHUNK; ++cc) red[tid][cc] = acc[cc];
    __syncthreads();
    for (int off = 32; off >= 1; off >>= 1) {
        if (tid < off)
#pragma unroll
            for (int cc = 0; cc < CHUNK; ++cc) red[tid][cc] += red[tid + off][cc];
        __syncthreads();
    }
    if (tid == 0)
#pragma unroll
        for (int cc = 0; cc < CHUNK; ++cc) t[(long)d * CHUNK + cc] = red[0][cc];
}

__global__ void tm_apply_kernel(const float* __restrict__ mem2, const float* __restrict__ t,
                                float* __restrict__ p)
{
    int b = blockIdx.x;
    int tid = threadIdx.x;
    float acc[CHUNK];
#pragma unroll
    for (int cc = 0; cc < CHUNK; ++cc) acc[cc] = 0.f;
    const float* mb = mem2 + (long)b * POSE;
    for (int d = tid; d < POSE; d += 256) {
        float m = mb[d];
        const float* tr = t + (long)d * CHUNK;
#pragma unroll
        for (int cc = 0; cc < CHUNK; ++cc) acc[cc] += m * tr[cc];
    }
    __shared__ float red[256][CHUNK];
    __shared__ float soft[CHUNK];
#pragma unroll
    for (int cc = 0; cc < CHUNK; ++cc) red[tid][cc] = acc[cc];
    __syncthreads();
    for (int off = 128; off >= 1; off >>= 1) {
        if (tid < off)
#pragma unroll
            for (int cc = 0; cc < CHUNK; ++cc) red[tid][cc] += red[tid + off][cc];
        __syncthreads();
    }
    if (tid == 0) {
        float mx = red[0][0];
#pragma unroll
        for (int cc = 1; cc < CHUNK; ++cc) mx = fmaxf(mx, red[0][cc]);
        float sum = 0.f, e[CHUNK];
#pragma unroll
        for (int cc = 0; cc < CHUNK; ++cc) { e[cc] = expf(red[0][cc] - mx); sum += e[cc]; }
        float inv = 1.f / sum;
#pragma unroll
        for (int cc = 0; cc < CHUNK; ++cc) soft[cc] = e[cc] * inv;
    }
    __syncthreads();
    float* pb = p + (long)b * PRED * POSE;
    for (int idx = tid; idx < CHUNK * POSE; idx += 256) {
        int cc = idx / POSE;
        pb[idx] *= (1.f + soft[cc]);
    }
}

// ---------------- host launcher ----------------
extern "C" void kernel_launch(void* const* d_in, const int* in_sizes, int n_in,
                              void* d_out, int out_size)
{
    (void)in_sizes; (void)n_in; (void)out_size;
    const float* x       = (const float*)d_in[0];
    const float* conv1_w = (const float*)d_in[1];
    const float* conv1_b = (const float*)d_in[2];
    const float* bn1_g   = (const float*)d_in[3];
    const float* bn1_b   = (const float*)d_in[4];
    const float* bn1_m   = (const float*)d_in[5];
    const float* bn1_v   = (const float*)d_in[6];
    const float* conv2_w = (const float*)d_in[7];
    const float* conv2_b = (const float*)d_in[8];
    const float* bn2_g   = (const float*)d_in[9];
    const float* bn2_b   = (const float*)d_in[10];
    const float* bn2_m   = (const float*)d_in[11];
    const float* bn2_v   = (const float*)d_in[12];
    const float* sp_w1   = (const float*)d_in[13];
    const float* sp_b1   = (const float*)d_in[14];
    const float* sp_w2   = (const float*)d_in[15];
    const float* sp_b2   = (const float*)d_in[16];
    const float* tmc_w1  = (const float*)d_in[17];
    const float* tmc_b1  = (const float*)d_in[18];
    const float* tmc_w2  = (const float*)d_in[19];
    const float* tmc_b2  = (const float*)d_in[20];
    const float* tmm_w1  = (const float*)d_in[21];
    const float* tmm_b1  = (const float*)d_in[22];
    const float* tmm_w2  = (const float*)d_in[23];
    const float* tmm_b2  = (const float*)d_in[24];
    const float* post_w1 = (const float*)d_in[25];
    const float* post_b1 = (const float*)d_in[26];
    const float* post_w2 = (const float*)d_in[27];
    const float* post_b2 = (const float*)d_in[28];

    unsigned short *Ah, *Hh, *W1h, *W2h, *Xth, *P1h, *Wc1h, *Wc2h;
    unsigned short *Wm, *W2sh, *W2th, *tmph;
    float *bm, *p2, *mem, *mem2, *s1, *penc, *t;
    cudaGetSymbolAddress((void**)&Ah, g_Ah);
    cudaGetSymbolAddress((void**)&Hh, g_Hh);
    cudaGetSymbolAddress((void**)&W1h, g_W1h);
    cudaGetSymbolAddress((void**)&W2h, g_W2h);
    cudaGetSymbolAddress((void**)&Xth, g_Xth);
    cudaGetSymbolAddress((void**)&P1h, g_P1h);
    cudaGetSymbolAddress((void**)&Wc1h, g_Wc1h);
    cudaGetSymbolAddress((void**)&Wc2h, g_Wc2h);
    cudaGetSymbolAddress((void**)&Wm, g_Wm);
    cudaGetSymbolAddress((void**)&bm, g_bm);
    cudaGetSymbolAddress((void**)&W2sh, g_W2sh);
    cudaGetSymbolAddress((void**)&W2th, g_W2th);
    cudaGetSymbolAddress((void**)&tmph, g_tmph);
    cudaGetSymbolAddress((void**)&p2, g_p2);
    cudaGetSymbolAddress((void**)&mem, g_mem);
    cudaGetSymbolAddress((void**)&mem2, g_mem2);
    cudaGetSymbolAddress((void**)&s1, g_s1);
    cudaGetSymbolAddress((void**)&penc, g_penc);
    cudaGetSymbolAddress((void**)&t, g_t);

    cudaFuncSetAttribute(mma_gemm<0, false, 128>, cudaFuncAttributeMaxDynamicSharedMemorySize, GSMEM_B);
    cudaFuncSetAttribute(mma_gemm<1, false, 128>, cudaFuncAttributeMaxDynamicSharedMemorySize, GSMEM_B);
    cudaFuncSetAttribute(mma_gemm<2, true, 128>,  cudaFuncAttributeMaxDynamicSharedMemorySize, GSMEM_B);
    cudaFuncSetAttribute(mma_gemm<3, true, 128>,  cudaFuncAttributeMaxDynamicSharedMemorySize, GSMEM_B);
    cudaFuncSetAttribute(mma_gemm<2, true, 64>,   cudaFuncAttributeMaxDynamicSharedMemorySize, GSMEM_B);
    cudaFuncSetAttribute(mma_gemm<3, true, 64>,   cudaFuncAttributeMaxDynamicSharedMemorySize, GSMEM_B);

    // conversions (all independent)
    cvt_convw<<<128, 256>>>(conv1_w, Wc1h, PRIOR, CIN1P);
    cvt_xT<<<dim3(POSE / 64, BATCH), 256>>>(x, Xth);
    cvt_h4<<<512, 256>>>((const float4*)post_w1, (ushort4*)W1h, POSE * POSE / 4);
    cvt_h4<<<512, 256>>>((const float4*)post_w2, (ushort4*)W2h, POSE * POSE / 4);
    cvt_convw<<<256, 256>>>(conv2_w, Wc2h, PRED, CIN2P);
    cvt_h4<<<512, 256>>>((const float4*)sp_w1,  (ushort4*)Wm,                          POSE * KENC / 4);
    cvt_h4<<<512, 256>>>((const float4*)tmc_w1, (ushort4*)(Wm + (size_t)POSE * KENC), POSE * KENC / 4);
    cvt_h4<<<64, 256>>>((const float4*)sp_w2,  (ushort4*)W2sh, POSE * POSE / 4);
    cvt_h4<<<64, 256>>>((const float4*)tmc_w2, (ushort4*)W2th, POSE * POSE / 4);
    cudaMemcpyAsync(bm, sp_b1, POSE * sizeof(float), cudaMemcpyDeviceToDevice);
    cudaMemcpyAsync(bm + POSE, tmc_b1, POSE * sizeof(float), cudaMemcpyDeviceToDevice);
    cvt_xrows<<<BATCH * PRIOR, 256>>>(x, Ah);

    // conv1: rows 0..127 (MT=128) + rows 128..191 (MT=64)  -> P1T fp16
    mma_gemm<2, true, 128><<<dim3(POSE / GBN, 1, BATCH), 256, GSMEM_B>>>(
        Wc1h, KC1, 0, Xth, KC1, CIN1P, 0,
        conv1_b, bn1_g, bn1_b, bn1_m, bn1_v, nullptr, P1h);
    mma_gemm<2, true, 64><<<dim3(POSE / GBN, 1, BATCH), 256, GSMEM_B>>>(
        Wc1h, KC1, 128, Xth, KC1, CIN1P, 0,
        conv1_b, bn1_g, bn1_b, bn1_m, bn1_v, nullptr, P1h);
    // conv2: same split -> p2 fp32 + Ah fp16 rows (frames >= CHUNK)
    mma_gemm<3, true, 128><<<dim3(POSE / GBN, 1, BATCH), 256, GSMEM_B>>>(
        Wc2h, KC2, 0, P1h, KC2, CIN2P, 0,
        conv2_b, bn2_g, bn2_b, bn2_m, bn2_v, p2, Ah);
    mma_gemm<3, true, 64><<<dim3(POSE / GBN, 1, BATCH), 256, GSMEM_B>>>(
        Wc2h, KC2, 128, P1h, KC2, CIN2P, 0,
        conv2_b, bn2_g, bn2_b, bn2_m, bn2_v, p2, Ah);

    // encoder layer-1 on HMMA: A = tail rows of Ah (frames 50..59), B = Wm [1536,7680]
    mma_gemm<1, false, 128><<<dim3(2 * POSE / GBN, BATCH / 128), 256, GSMEM_B>>>(
        Ah + (size_t)(PRIOR - CHUNK) * POSE, (long)FRAMES * POSE, 0, Wm, KENC, 0, 2 * POSE,
        bm, nullptr, nullptr, nullptr, nullptr, nullptr, tmph);
    // encoder layer-2 on HMMA: mem / mem2 fp32
    mma_gemm<0, false, 128><<<dim3(POSE / GBN, BATCH / 128), 256, GSMEM_B>>>(
        tmph, 2 * POSE, 0, W2sh, POSE, 0, POSE,
        sp_b2, nullptr, nullptr, nullptr, nullptr, mem, nullptr);
    mma_gemm<0, false, 128><<<dim3(POSE / GBN, BATCH / 128), 256, GSMEM_B>>>(
        tmph + POSE, 2 * POSE, 0, W2th, POSE, 0, POSE,
        tmc_b2, nullptr, nullptr, nullptr, nullptr, mem2, nullptr);

    // gates + tmm encoder (FFMA, tiny)
    sp_gate_kernel<<<BATCH, CHUNK * 32>>>(mem, p2);
    sgemm_nt<32, 128, 16, 4, 8><<<dim3(1, BATCH / 32), 128>>>(
        p2, (long)PRED * POSE, tmm_w1, tmm_b1, s1, CHUNK, BATCH, CHUNK, KENC);
    sgemm_nt<32, 128, 16, 4, 8><<<dim3(1, BATCH / 32), 128>>>(
        s1, CHUNK, tmm_w2, tmm_b2, penc, CHUNK, BATCH, CHUNK, CHUNK);
    tm_t_kernel<<<POSE, 64>>>(mem2, penc, t);
    tm_apply_kernel<<<BATCH, 256>>>(mem2, t, p2);

    // fill Ah gated chunk rows 60..69 per batch
    cvt_chunk<<<BATCH * CHUNK, 256>>>(p2, Ah);

    // post header on HMMA tensor path (single-pass fp16)
    mma_gemm<1, false, 128><<<dim3(POSE / GBN, MROWS / 128), 256, GSMEM_B>>>(
        Ah, POSE, 0, W1h, POSE, 0, POSE,
        post_b1, nullptr, nullptr, nullptr, nullptr, nullptr, Hh);
    mma_gemm<0, false, 128><<<dim3(POSE / GBN, MROWS / 128), 256, GSMEM_B>>>(
        Hh, POSE, 0, W2h, POSE, 0, POSE,
        post_b2, nullptr, nullptr, nullptr, nullptr, (float*)d_out, nullptr);
}